// round 1
// baseline (speedup 1.0000x reference)
#include <cuda_runtime.h>
#include <cuda_bf16.h>
#include <cstdint>

// Problem constants
#define PB   128      // batch (attention attends across this dim)
#define PN   256      // tokens per sample
#define PD   1024     // d_model
#define PH   16       // heads
#define PDK  64       // d_k
#define PM   (PB*PN)  // 32768 rows for projection GEMMs

// Scratch (static device globals; allocation at module load, allowed)
__device__ float g_Q[PH*PN*PB*PDK];  // [h][n][b][dk]
__device__ float g_K[PH*PN*PB*PDK];
__device__ float g_V[PH*PN*PB*PDK];
__device__ float g_O[PM*PD];         // (b,n,d) attention output

// ---------- packed f32x2 helpers (Blackwell FFMA2 path) ----------
__device__ __forceinline__ unsigned long long pk2(float x, float y) {
    unsigned long long r;
    asm("mov.b64 %0, {%1,%2};" : "=l"(r) : "f"(x), "f"(y));
    return r;
}
__device__ __forceinline__ float2 upk(unsigned long long v) {
    float2 r;
    asm("mov.b64 {%0,%1}, %2;" : "=f"(r.x), "=f"(r.y) : "l"(v));
    return r;
}
__device__ __forceinline__ unsigned long long ffma2(unsigned long long a,
                                                    unsigned long long b,
                                                    unsigned long long c) {
    unsigned long long d;
    asm("fma.rn.f32x2 %0, %1, %2, %3;" : "=l"(d) : "l"(a), "l"(b), "l"(c));
    return d;
}

// ============================================================================
// GEMM: Y[m,e] = sum_d X[m,d] * W[e,d] + bias[e]   (both operands K-contiguous)
// M=32768, N=1024, K=1024. Tile 128x128x8, 256 threads, 8x8 per thread,
// FFMA2 with m-pairs (a-pairs loaded directly as 64-bit from SMEM).
// mode 0: scatter to head layout [h][n][b][dk]; mode 1: row-major m*1024+e.
// ============================================================================
__global__ __launch_bounds__(256, 2)
void gemm_nt_kernel(const float* __restrict__ X, const float* __restrict__ W,
                    const float* __restrict__ bias, float* __restrict__ Y,
                    int mode)
{
    __shared__ float As[8][128];   // As[k][m]
    __shared__ float Bs[8][128];   // Bs[k][n]

    const int tid = threadIdx.x;
    const int m0 = blockIdx.y * 128;
    const int n0 = blockIdx.x * 128;

    const int w  = tid >> 5, l = tid & 31;
    const int warp_m = w >> 1, warp_n = w & 1;     // 4x2 warps
    const int lm = l >> 3,  ln = l & 7;            // 4x8 lanes
    const int mBase = warp_m * 32 + lm * 8;        // 8 consecutive m
    const int nBase = warp_n * 64 + ln * 8;        // 8 consecutive n

    // global load assignment: one float4 of X and one of W per thread per tile
    const int ar = tid >> 1;          // row within tile (0..127)
    const int ak = (tid & 1) * 4;     // k offset (0 or 4)
    const float* Xp = X + (size_t)(m0 + ar) * PD + ak;
    const float* Wp = W + (size_t)(n0 + ar) * PD + ak;

    unsigned long long acc[4][8];     // [m-pair][n], each holds (c[2mp][j], c[2mp+1][j])
#pragma unroll
    for (int i = 0; i < 4; i++)
#pragma unroll
        for (int j = 0; j < 8; j++) acc[i][j] = 0ull;

    float4 fa = *(const float4*)Xp;
    float4 fb = *(const float4*)Wp;

    for (int kk = 0; kk < PD / 8; ++kk) {
        // commit prefetched tile to SMEM (transposed)
        As[ak + 0][ar] = fa.x; As[ak + 1][ar] = fa.y;
        As[ak + 2][ar] = fa.z; As[ak + 3][ar] = fa.w;
        Bs[ak + 0][ar] = fb.x; Bs[ak + 1][ar] = fb.y;
        Bs[ak + 2][ar] = fb.z; Bs[ak + 3][ar] = fb.w;
        __syncthreads();

        if (kk + 1 < PD / 8) {
            fa = *(const float4*)(Xp + (size_t)(kk + 1) * 8);
            fb = *(const float4*)(Wp + (size_t)(kk + 1) * 8);
        }

#pragma unroll
        for (int k = 0; k < 8; ++k) {
            const unsigned long long* app =
                (const unsigned long long*)&As[k][mBase];
            unsigned long long ap0 = app[0], ap1 = app[1],
                               ap2 = app[2], ap3 = app[3];
            float4 b0 = *(const float4*)&Bs[k][nBase];
            float4 b1 = *(const float4*)&Bs[k][nBase + 4];
            unsigned long long bp[8];
            bp[0] = pk2(b0.x, b0.x); bp[1] = pk2(b0.y, b0.y);
            bp[2] = pk2(b0.z, b0.z); bp[3] = pk2(b0.w, b0.w);
            bp[4] = pk2(b1.x, b1.x); bp[5] = pk2(b1.y, b1.y);
            bp[6] = pk2(b1.z, b1.z); bp[7] = pk2(b1.w, b1.w);
#pragma unroll
            for (int j = 0; j < 8; j++) {
                acc[0][j] = ffma2(ap0, bp[j], acc[0][j]);
                acc[1][j] = ffma2(ap1, bp[j], acc[1][j]);
                acc[2][j] = ffma2(ap2, bp[j], acc[2][j]);
                acc[3][j] = ffma2(ap3, bp[j], acc[3][j]);
            }
        }
        __syncthreads();
    }

    // epilogue
    const int e0 = n0 + nBase;
    float4 bb0 = *(const float4*)&bias[e0];
    float4 bb1 = *(const float4*)&bias[e0 + 4];
    float bs[8] = {bb0.x, bb0.y, bb0.z, bb0.w, bb1.x, bb1.y, bb1.z, bb1.w};

#pragma unroll
    for (int mp = 0; mp < 4; ++mp) {
        float lo[8], hi[8];
#pragma unroll
        for (int j = 0; j < 8; j++) {
            float2 v = upk(acc[mp][j]);
            lo[j] = v.x + bs[j];
            hi[j] = v.y + bs[j];
        }
#pragma unroll
        for (int half = 0; half < 2; ++half) {
            const float* r = half ? hi : lo;
            const int m = m0 + mBase + 2 * mp + half;
            float* dst;
            if (mode == 0) {
                const int b = m >> 8;        // m / N
                const int n = m & 255;       // m % N
                const int h = e0 >> 6;       // e / 64
                const int dk = e0 & 63;      // e % 64
                dst = Y + ((((size_t)h * PN + n) * PB + b) * PDK + dk);
            } else {
                dst = Y + (size_t)m * PD + e0;
            }
            float4 o0 = {r[0], r[1], r[2], r[3]};
            float4 o1 = {r[4], r[5], r[6], r[7]};
            ((float4*)dst)[0] = o0;
            ((float4*)dst)[1] = o1;
        }
    }
}

// Fused QKV wrapper: grid.z selects which projection
__global__ __launch_bounds__(256, 2)
void gemm_qkv_kernel(const float* __restrict__ q_in, const float* __restrict__ k_in,
                     const float* __restrict__ v_in,
                     const float* __restrict__ Wq, const float* __restrict__ bq,
                     const float* __restrict__ Wk, const float* __restrict__ bk,
                     const float* __restrict__ Wv, const float* __restrict__ bv)
{
    // Delegate via pointer select, then inline the same body by tail-calling
    // the device path: easiest correct form is to duplicate the launch per z on
    // host; kept for potential future use.
}

// ============================================================================
// Attention: one CTA per (h,n). Thread i = batch row i (128 threads).
// Q,K,V tiles are contiguous 32KB blocks in [h][n][b][dk] layout.
// ============================================================================
#define ATTN_SMEM_FLOATS (PB*PDK + PB*129)
__global__ __launch_bounds__(128)
void attn_kernel(const float* __restrict__ Q, const float* __restrict__ K,
                 const float* __restrict__ V, float* __restrict__ O)
{
    extern __shared__ float sm[];
    float* Ks = sm;                 // 128*64 floats (reused for V)
    float* S  = sm + PB * PDK;      // 128 rows, stride 129 (conflict-free)

    const int hn = blockIdx.x;      // h*N + n
    const int h  = hn >> 8;
    const int n  = hn & 255;
    const int b  = threadIdx.x;     // batch row
    const size_t base = (size_t)hn * (PB * PDK);

    // cooperative load of K tile (contiguous 32KB)
    const float4* Kg  = (const float4*)(K + base);
    float4*       Ks4 = (float4*)Ks;
#pragma unroll
    for (int i = 0; i < 16; i++) Ks4[b + 128 * i] = Kg[b + 128 * i];

    // this thread's Q row into registers as f32x2 pairs
    unsigned long long q[32];
    const unsigned long long* Qg = (const unsigned long long*)(Q + base + b * PDK);
#pragma unroll
    for (int i = 0; i < 32; i++) q[i] = Qg[i];
    __syncthreads();

    // scores: s[c] = 0.125 * dot(Q[b], K[c])
    float mx = -1e30f;
    for (int c = 0; c < 128; ++c) {
        const unsigned long long* kr = (const unsigned long long*)(Ks + c * PDK);
        unsigned long long a = 0ull;
#pragma unroll
        for (int i = 0; i < 32; i++) a = ffma2(q[i], kr[i], a);
        float2 v = upk(a);
        float s = (v.x + v.y) * 0.125f;
        S[b * 129 + c] = s;
        mx = fmaxf(mx, s);
    }

    // softmax over own row (normalization deferred to output scaling)
    float sum = 0.f;
    for (int c = 0; c < 128; ++c) {
        float e = __expf(S[b * 129 + c] - mx);
        S[b * 129 + c] = e;
        sum += e;
    }
    const float inv = 1.0f / sum;
    __syncthreads();   // all threads done reading Ks

    // overwrite Ks with V tile
    const float4* Vg = (const float4*)(V + base);
#pragma unroll
    for (int i = 0; i < 16; i++) Ks4[b + 128 * i] = Vg[b + 128 * i];
    __syncthreads();

    // PV: out[b][d] = inv * sum_c p[b][c] * V[c][d]
    unsigned long long acc[32];
#pragma unroll
    for (int i = 0; i < 32; i++) acc[i] = 0ull;
    for (int c = 0; c < 128; ++c) {
        float p = S[b * 129 + c];
        unsigned long long pp = pk2(p, p);
        const unsigned long long* vr = (const unsigned long long*)(Ks + c * PDK);
#pragma unroll
        for (int i = 0; i < 32; i++) acc[i] = ffma2(pp, vr[i], acc[i]);
    }

    // store to (b, n, h*64 + d)
    float* dst = O + ((size_t)(b * PN + n)) * PD + h * PDK;
#pragma unroll
    for (int i = 0; i < 32; i += 2) {
        float2 x = upk(acc[i]);
        float2 y = upk(acc[i + 1]);
        float4 o = {x.x * inv, x.y * inv, y.x * inv, y.y * inv};
        ((float4*)dst)[i >> 1] = o;
    }
}

// ============================================================================
// Launch
// ============================================================================
extern "C" void kernel_launch(void* const* d_in, const int* in_sizes, int n_in,
                              void* d_out, int out_size)
{
    const float* query = (const float*)d_in[0];
    const float* key_i = (const float*)d_in[1];
    const float* value = (const float*)d_in[2];
    const float* Wq = (const float*)d_in[3];
    const float* bq = (const float*)d_in[4];
    const float* Wk = (const float*)d_in[5];
    const float* bk = (const float*)d_in[6];
    const float* Wv = (const float*)d_in[7];
    const float* bv = (const float*)d_in[8];
    const float* Wo = (const float*)d_in[9];
    const float* bo = (const float*)d_in[10];
    float* out = (float*)d_out;

    float *gQ, *gK, *gV, *gO;
    cudaGetSymbolAddress((void**)&gQ, g_Q);
    cudaGetSymbolAddress((void**)&gK, g_K);
    cudaGetSymbolAddress((void**)&gV, g_V);
    cudaGetSymbolAddress((void**)&gO, g_O);

    const size_t attn_smem = (size_t)ATTN_SMEM_FLOATS * sizeof(float);
    cudaFuncSetAttribute(attn_kernel,
                         cudaFuncAttributeMaxDynamicSharedMemorySize,
                         (int)attn_smem);

    dim3 gblk(256);
    dim3 ggrid(PD / 128, PM / 128);   // (8, 256)

    gemm_nt_kernel<<<ggrid, gblk>>>(query, Wq, bq, gQ, 0);
    gemm_nt_kernel<<<ggrid, gblk>>>(key_i, Wk, bk, gK, 0);
    gemm_nt_kernel<<<ggrid, gblk>>>(value, Wv, bv, gV, 0);

    attn_kernel<<<PH * PN, 128, attn_smem>>>(gQ, gK, gV, gO);

    gemm_nt_kernel<<<ggrid, gblk>>>(gO, Wo, bo, out, 1);
}

// round 4
// speedup vs baseline: 2.2298x; 2.2298x over previous
#include <cuda_runtime.h>
#include <cuda_bf16.h>
#include <cstdint>

// Problem constants
#define PB   128
#define PN   256
#define PD   1024
#define PH   16
#define PDK  64
#define PM   (PB*PN)   // 32768

// ---------------------------------------------------------------------------
// Global scratch
// ---------------------------------------------------------------------------
__device__ float g_Q[PM*PD];   // fp32 projections, row-major (b*N+n, e)
__device__ float g_K[PM*PD];
__device__ float g_V[PM*PD];

__device__ __nv_bfloat16 g_qh[PM*PD], g_ql[PM*PD];
__device__ __nv_bfloat16 g_kh[PM*PD], g_kl[PM*PD];
__device__ __nv_bfloat16 g_vh[PM*PD], g_vl[PM*PD];
__device__ __nv_bfloat16 g_oh[PM*PD], g_ol[PM*PD];
__device__ __nv_bfloat16 g_wh[4][PD*PD], g_wl[4][PD*PD];

// ---------------------------------------------------------------------------
// helpers
// ---------------------------------------------------------------------------
__device__ __forceinline__ uint32_t smem_u32(const void* p) {
    uint32_t a;
    asm("{ .reg .u64 t; cvta.to.shared.u64 t, %1; cvt.u32.u64 %0, t; }"
        : "=r"(a) : "l"(p));
    return a;
}
// pack two floats -> bf16x2 (low = x, high = y)
__device__ __forceinline__ uint32_t bf2(float x, float y) {
    uint32_t r;
    asm("cvt.rn.bf16x2.f32 %0, %2, %1;" : "=r"(r) : "f"(x), "f"(y));
    return r;
}
__device__ __forceinline__ unsigned long long pk2(float x, float y) {
    unsigned long long r;
    asm("mov.b64 %0, {%1,%2};" : "=l"(r) : "f"(x), "f"(y));
    return r;
}
__device__ __forceinline__ float2 upk(unsigned long long v) {
    float2 r;
    asm("mov.b64 {%0,%1}, %2;" : "=f"(r.x), "=f"(r.y) : "l"(v));
    return r;
}
__device__ __forceinline__ unsigned long long ffma2(unsigned long long a,
                                                    unsigned long long b,
                                                    unsigned long long c) {
    unsigned long long d;
    asm("fma.rn.f32x2 %0, %1, %2, %3;" : "=l"(d) : "l"(a), "l"(b), "l"(c));
    return d;
}
__device__ __forceinline__ void cpa16(uint32_t s, const void* g) {
    asm volatile("cp.async.cg.shared.global [%0], [%1], 16;"
                 :: "r"(s), "l"(g) : "memory");
}
__device__ __forceinline__ void ldsm4(uint32_t* r, uint32_t addr) {
    asm volatile("ldmatrix.sync.aligned.m8n8.x4.shared.b16 {%0,%1,%2,%3}, [%4];"
                 : "=r"(r[0]), "=r"(r[1]), "=r"(r[2]), "=r"(r[3]) : "r"(addr));
}
__device__ __forceinline__ void mma_bf16(float* c, const uint32_t* a,
                                         const uint32_t* b) {
    asm volatile("mma.sync.aligned.m16n8k16.row.col.f32.bf16.bf16.f32 "
                 "{%0,%1,%2,%3}, {%4,%5,%6,%7}, {%8,%9}, {%0,%1,%2,%3};"
                 : "+f"(c[0]), "+f"(c[1]), "+f"(c[2]), "+f"(c[3])
                 : "r"(a[0]), "r"(a[1]), "r"(a[2]), "r"(a[3]),
                   "r"(b[0]), "r"(b[1]));
}

// ---------------------------------------------------------------------------
// split: fp32 -> bf16 hi + bf16 lo (residual)
// ---------------------------------------------------------------------------
__global__ __launch_bounds__(256)
void split_kernel(const float* __restrict__ src,
                  __nv_bfloat16* __restrict__ hi,
                  __nv_bfloat16* __restrict__ lo, int n4)
{
    int i = blockIdx.x * 256 + threadIdx.x;
    if (i >= n4) return;
    float4 v = ((const float4*)src)[i];
    uint32_t h01 = bf2(v.x, v.y);
    uint32_t h23 = bf2(v.z, v.w);
    float r0 = v.x - __uint_as_float(h01 << 16);
    float r1 = v.y - __uint_as_float(h01 & 0xffff0000u);
    float r2 = v.z - __uint_as_float(h23 << 16);
    float r3 = v.w - __uint_as_float(h23 & 0xffff0000u);
    ((uint2*)hi)[i] = make_uint2(h01, h23);
    ((uint2*)lo)[i] = make_uint2(bf2(r0, r1), bf2(r2, r3));
}

// ---------------------------------------------------------------------------
// GEMM: Y[m,e] = sum_d A[m,d]*B[e,d] + bias[e], 3-term bf16 split.
// A = Ah+Al (M x K), B = Bh+Bl (N x K), both row-major K-contiguous bf16.
// CTA tile 128x128, KC=32, double-buffered cp.async, mma.sync m16n8k16.
// ---------------------------------------------------------------------------
#define GKC  32
#define GNK  (PD/GKC)        // 32 chunks
#define STGB (32*1024)       // per-stage smem: 4 subtiles x 8KB
#define GEMM_SMEM (2*STGB)

// swizzled byte offset within an 8KB subtile (128 rows x 32 bf16, 64B rows)
__device__ __forceinline__ uint32_t sw_off(int r, int c16) {
    return (uint32_t)(r * 64 + ((c16 ^ ((r >> 1) & 3)) << 4));
}

__device__ __forceinline__ void gemm_load_stage(
    uint32_t sbase, int stage, int kk, int tid,
    const __nv_bfloat16* Ah0, const __nv_bfloat16* Al0,
    const __nv_bfloat16* Bh0, const __nv_bfloat16* Bl0)
{
    const uint32_t sb = sbase + (uint32_t)stage * STGB;
    const __nv_bfloat16* gp[4] = {Ah0, Al0, Bh0, Bl0};
#pragma unroll
    for (int sub = 0; sub < 4; ++sub) {
#pragma unroll
        for (int it = 0; it < 2; ++it) {
            int chunk = tid + 256 * it;
            int r = chunk >> 2, c16 = chunk & 3;
            cpa16(sb + sub * 8192 + sw_off(r, c16),
                  gp[sub] + (size_t)r * PD + kk * GKC + c16 * 8);
        }
    }
    asm volatile("cp.async.commit_group;" ::: "memory");
}

__global__ __launch_bounds__(256, 1)
void gemm_bf16x3(const __nv_bfloat16* __restrict__ Ah,
                 const __nv_bfloat16* __restrict__ Al,
                 const __nv_bfloat16* __restrict__ Bh,
                 const __nv_bfloat16* __restrict__ Bl,
                 const float* __restrict__ bias,
                 float* __restrict__ Y)
{
    extern __shared__ char smc[];
    const uint32_t sbase = smem_u32(smc);
    const int tid = threadIdx.x;
    const int wid = tid >> 5, lane = tid & 31;
    const int m0 = blockIdx.y * 128, n0 = blockIdx.x * 128;
    const int wm = wid & 3, wn = wid >> 2;

    const __nv_bfloat16* Ah0 = Ah + (size_t)m0 * PD;
    const __nv_bfloat16* Al0 = Al + (size_t)m0 * PD;
    const __nv_bfloat16* Bh0 = Bh + (size_t)n0 * PD;
    const __nv_bfloat16* Bl0 = Bl + (size_t)n0 * PD;

    float acc[2][8][4];
#pragma unroll
    for (int mi = 0; mi < 2; ++mi)
#pragma unroll
        for (int ni = 0; ni < 8; ++ni)
#pragma unroll
            for (int q = 0; q < 4; ++q) acc[mi][ni][q] = 0.f;

    gemm_load_stage(sbase, 0, 0, tid, Ah0, Al0, Bh0, Bl0);

    // precompute ldmatrix lane addressing pieces
    const int a_row = wm * 32 + (lane & 15);          // + mi*16
    const int a_c16h = lane >> 4;                      // + ks*2
    const int b_row = wn * 64 + ((lane >> 4) << 3) + (lane & 7);  // + bi*16
    const int b_c16h = (lane >> 3) & 1;                // + ks*2

    for (int kk = 0; kk < GNK; ++kk) {
        if (kk + 1 < GNK) {
            gemm_load_stage(sbase, (kk + 1) & 1, kk + 1, tid, Ah0, Al0, Bh0, Bl0);
            asm volatile("cp.async.wait_group 1;" ::: "memory");
        } else {
            asm volatile("cp.async.wait_group 0;" ::: "memory");
        }
        __syncthreads();

        const uint32_t sb = sbase + (uint32_t)(kk & 1) * STGB;
#pragma unroll
        for (int ks = 0; ks < 2; ++ks) {
            uint32_t ahi[2][4], alo[2][4];
#pragma unroll
            for (int mi = 0; mi < 2; ++mi) {
                int r = a_row + mi * 16;
                int c = ks * 2 + a_c16h;
                ldsm4(ahi[mi], sb +        sw_off(r, c));
                ldsm4(alo[mi], sb + 8192 + sw_off(r, c));
            }
#pragma unroll
            for (int bi = 0; bi < 4; ++bi) {
                uint32_t bhi[4], blo[4];
                int r = b_row + bi * 16;
                int c = ks * 2 + b_c16h;
                ldsm4(bhi, sb + 16384 + sw_off(r, c));
                ldsm4(blo, sb + 24576 + sw_off(r, c));
#pragma unroll
                for (int mi = 0; mi < 2; ++mi) {
#pragma unroll
                    for (int half = 0; half < 2; ++half) {
                        float* c4 = acc[mi][bi * 2 + half];
                        mma_bf16(c4, ahi[mi], &bhi[half * 2]);
                        mma_bf16(c4, ahi[mi], &blo[half * 2]);
                        mma_bf16(c4, alo[mi], &bhi[half * 2]);
                    }
                }
            }
        }
        __syncthreads();
    }

    // epilogue: frag c layout: thread t -> rows (t/4, t/4+8), cols (t%4)*2,+1
    const int trow = lane >> 2;
    const int tcol = (lane & 3) * 2;
#pragma unroll
    for (int mi = 0; mi < 2; ++mi) {
        const int r0 = m0 + wm * 32 + mi * 16 + trow;
#pragma unroll
        for (int ni = 0; ni < 8; ++ni) {
            const int col = n0 + wn * 64 + ni * 8 + tcol;
            float bx = bias[col], by = bias[col + 1];
            float* c4 = acc[mi][ni];
            *(float2*)(Y + (size_t)r0 * PD + col) =
                make_float2(c4[0] + bx, c4[1] + by);
            *(float2*)(Y + (size_t)(r0 + 8) * PD + col) =
                make_float2(c4[2] + bx, c4[3] + by);
        }
    }
}

// ---------------------------------------------------------------------------
// Attention: one CTA per (h,n); thread = batch row. Row-major gather of
// Q/K/V; writes bf16 hi/lo split of output directly.
// ---------------------------------------------------------------------------
#define ATTN_SMEM_FLOATS (PB*PDK + PB*129)
__global__ __launch_bounds__(128)
void attn_kernel(const float* __restrict__ Q, const float* __restrict__ K,
                 const float* __restrict__ V,
                 __nv_bfloat16* __restrict__ Oh,
                 __nv_bfloat16* __restrict__ Ol)
{
    extern __shared__ float smf[];
    float* Ks = smf;              // [128][64]
    float* S  = smf + PB * PDK;   // [128] rows, stride 129

    const int hn = blockIdx.x;
    const int h  = hn >> 8;
    const int n  = hn & 255;
    const int b  = threadIdx.x;
    const size_t rowoff = (size_t)n * PD + h * PDK;

    // gather K -> Ks, Q -> S (staging); 256B-contiguous segments
#pragma unroll
    for (int j = 0; j < 16; ++j) {
        int i = b + 128 * j;
        int r = i >> 4, c4 = i & 15;
        size_t g = (size_t)r * PD * PN + rowoff;
        ((float4*)Ks)[r * 16 + c4] = *((const float4*)(K + g) + c4);
        ((float4*)S )[r * 16 + c4] = *((const float4*)(Q + g) + c4);
    }
    __syncthreads();

    unsigned long long q[32];
    const unsigned long long* qr = (const unsigned long long*)(S + b * PDK);
#pragma unroll
    for (int i = 0; i < 32; ++i) q[i] = qr[i];
    __syncthreads();   // everyone has q before S becomes scores

    float mx = -1e30f;
    for (int c = 0; c < 128; ++c) {
        const unsigned long long* kr = (const unsigned long long*)(Ks + c * PDK);
        unsigned long long a = 0ull;
#pragma unroll
        for (int i = 0; i < 32; ++i) a = ffma2(q[i], kr[i], a);
        float2 v = upk(a);
        float s = (v.x + v.y) * 0.125f;
        S[b * 129 + c] = s;
        mx = fmaxf(mx, s);
    }

    float sum = 0.f;
    for (int c = 0; c < 128; ++c) {
        float e = __expf(S[b * 129 + c] - mx);
        S[b * 129 + c] = e;
        sum += e;
    }
    const float inv = 1.0f / sum;
    __syncthreads();

    // overwrite Ks with V
#pragma unroll
    for (int j = 0; j < 16; ++j) {
        int i = b + 128 * j;
        int r = i >> 4, c4 = i & 15;
        size_t g = (size_t)r * PD * PN + rowoff;
        ((float4*)Ks)[r * 16 + c4] = *((const float4*)(V + g) + c4);
    }
    __syncthreads();

    unsigned long long acc[32];
#pragma unroll
    for (int i = 0; i < 32; ++i) acc[i] = 0ull;
    for (int c = 0; c < 128; ++c) {
        float p = S[b * 129 + c];
        unsigned long long pp = pk2(p, p);
        const unsigned long long* vr = (const unsigned long long*)(Ks + c * PDK);
#pragma unroll
        for (int i = 0; i < 32; ++i) acc[i] = ffma2(pp, vr[i], acc[i]);
    }

    // write hi/lo bf16 split of output at (b*PN+n)*PD + h*64
    const size_t obase = ((size_t)(b * PN + n)) * PD + h * PDK;
#pragma unroll
    for (int i = 0; i < 32; i += 2) {
        float2 x = upk(acc[i]);
        float2 y = upk(acc[i + 1]);
        float f0 = x.x * inv, f1 = x.y * inv;
        float f2 = y.x * inv, f3 = y.y * inv;
        uint32_t h01 = bf2(f0, f1), h23 = bf2(f2, f3);
        float r0 = f0 - __uint_as_float(h01 << 16);
        float r1 = f1 - __uint_as_float(h01 & 0xffff0000u);
        float r2 = f2 - __uint_as_float(h23 << 16);
        float r3 = f3 - __uint_as_float(h23 & 0xffff0000u);
        ((uint2*)(Oh + obase))[i >> 1] = make_uint2(h01, h23);
        ((uint2*)(Ol + obase))[i >> 1] = make_uint2(bf2(r0, r1), bf2(r2, r3));
    }
}

// ---------------------------------------------------------------------------
extern "C" void kernel_launch(void* const* d_in, const int* in_sizes, int n_in,
                              void* d_out, int out_size)
{
    const float* query = (const float*)d_in[0];
    const float* key_i = (const float*)d_in[1];
    const float* value = (const float*)d_in[2];
    const float* Wq = (const float*)d_in[3];
    const float* bq = (const float*)d_in[4];
    const float* Wk = (const float*)d_in[5];
    const float* bk = (const float*)d_in[6];
    const float* Wv = (const float*)d_in[7];
    const float* bv = (const float*)d_in[8];
    const float* Wo = (const float*)d_in[9];
    const float* bo = (const float*)d_in[10];
    float* out = (float*)d_out;

    float *gQ, *gK, *gV;
    cudaGetSymbolAddress((void**)&gQ, g_Q);
    cudaGetSymbolAddress((void**)&gK, g_K);
    cudaGetSymbolAddress((void**)&gV, g_V);
    __nv_bfloat16 *qh, *ql, *kh, *kl, *vh, *vl, *oh, *ol, *wh, *wl;
    cudaGetSymbolAddress((void**)&qh, g_qh);
    cudaGetSymbolAddress((void**)&ql, g_ql);
    cudaGetSymbolAddress((void**)&kh, g_kh);
    cudaGetSymbolAddress((void**)&kl, g_kl);
    cudaGetSymbolAddress((void**)&vh, g_vh);
    cudaGetSymbolAddress((void**)&vl, g_vl);
    cudaGetSymbolAddress((void**)&oh, g_oh);
    cudaGetSymbolAddress((void**)&ol, g_ol);
    cudaGetSymbolAddress((void**)&wh, g_wh);
    cudaGetSymbolAddress((void**)&wl, g_wl);

    cudaFuncSetAttribute(gemm_bf16x3,
                         cudaFuncAttributeMaxDynamicSharedMemorySize, GEMM_SMEM);
    const size_t attn_smem = (size_t)ATTN_SMEM_FLOATS * sizeof(float);
    cudaFuncSetAttribute(attn_kernel,
                         cudaFuncAttributeMaxDynamicSharedMemorySize,
                         (int)attn_smem);

    const int nbig = PM * PD / 4, nw = PD * PD / 4;

    split_kernel<<<nbig / 256, 256>>>(query, qh, ql, nbig);
    split_kernel<<<nbig / 256, 256>>>(key_i, kh, kl, nbig);
    split_kernel<<<nbig / 256, 256>>>(value, vh, vl, nbig);
    split_kernel<<<nw / 256, 256>>>(Wq, wh + 0 * (size_t)PD * PD, wl + 0 * (size_t)PD * PD, nw);
    split_kernel<<<nw / 256, 256>>>(Wk, wh + 1 * (size_t)PD * PD, wl + 1 * (size_t)PD * PD, nw);
    split_kernel<<<nw / 256, 256>>>(Wv, wh + 2 * (size_t)PD * PD, wl + 2 * (size_t)PD * PD, nw);
    split_kernel<<<nw / 256, 256>>>(Wo, wh + 3 * (size_t)PD * PD, wl + 3 * (size_t)PD * PD, nw);

    dim3 gg(PD / 128, PM / 128);   // (8, 256)
    gemm_bf16x3<<<gg, 256, GEMM_SMEM>>>(qh, ql, wh + 0 * (size_t)PD * PD, wl + 0 * (size_t)PD * PD, bq, gQ);
    gemm_bf16x3<<<gg, 256, GEMM_SMEM>>>(kh, kl, wh + 1 * (size_t)PD * PD, wl + 1 * (size_t)PD * PD, bk, gK);
    gemm_bf16x3<<<gg, 256, GEMM_SMEM>>>(vh, vl, wh + 2 * (size_t)PD * PD, wl + 2 * (size_t)PD * PD, bv, gV);

    attn_kernel<<<PH * PN, 128, attn_smem>>>(gQ, gK, gV, oh, ol);

    gemm_bf16x3<<<gg, 256, GEMM_SMEM>>>(oh, ol, wh + 3 * (size_t)PD * PD, wl + 3 * (size_t)PD * PD, bo, out);
}

// round 5
// speedup vs baseline: 2.5502x; 1.1437x over previous
#include <cuda_runtime.h>
#include <cuda_bf16.h>
#include <cstdint>

// Problem constants
#define PB   128
#define PN   256
#define PD   1024
#define PH   16
#define PDK  64
#define PM   (PB*PN)   // 32768

// ---------------------------------------------------------------------------
// Global scratch
// ---------------------------------------------------------------------------
__device__ float g_Q[PM*PD];   // fp32 projections, row-major (b*N+n, e)
__device__ float g_K[PM*PD];
__device__ float g_V[PM*PD];

__device__ __nv_bfloat16 g_qh[PM*PD], g_ql[PM*PD];
__device__ __nv_bfloat16 g_kh[PM*PD], g_kl[PM*PD];
__device__ __nv_bfloat16 g_vh[PM*PD], g_vl[PM*PD];
__device__ __nv_bfloat16 g_oh[PM*PD], g_ol[PM*PD];
__device__ __nv_bfloat16 g_wh[4][PD*PD], g_wl[4][PD*PD];

// ---------------------------------------------------------------------------
// helpers
// ---------------------------------------------------------------------------
__device__ __forceinline__ uint32_t smem_u32(const void* p) {
    uint32_t a;
    asm("{ .reg .u64 t; cvta.to.shared.u64 t, %1; cvt.u32.u64 %0, t; }"
        : "=r"(a) : "l"(p));
    return a;
}
__device__ __forceinline__ uint32_t bf2(float x, float y) {
    uint32_t r;
    asm("cvt.rn.bf16x2.f32 %0, %2, %1;" : "=r"(r) : "f"(x), "f"(y));
    return r;
}
__device__ __forceinline__ unsigned long long pk2(float x, float y) {
    unsigned long long r;
    asm("mov.b64 %0, {%1,%2};" : "=l"(r) : "f"(x), "f"(y));
    return r;
}
__device__ __forceinline__ float2 upk(unsigned long long v) {
    float2 r;
    asm("mov.b64 {%0,%1}, %2;" : "=f"(r.x), "=f"(r.y) : "l"(v));
    return r;
}
__device__ __forceinline__ unsigned long long ffma2(unsigned long long a,
                                                    unsigned long long b,
                                                    unsigned long long c) {
    unsigned long long d;
    asm("fma.rn.f32x2 %0, %1, %2, %3;" : "=l"(d) : "l"(a), "l"(b), "l"(c));
    return d;
}
__device__ __forceinline__ void cpa16(uint32_t s, const void* g) {
    asm volatile("cp.async.cg.shared.global [%0], [%1], 16;"
                 :: "r"(s), "l"(g) : "memory");
}
__device__ __forceinline__ void ldsm4(uint32_t* r, uint32_t addr) {
    asm volatile("ldmatrix.sync.aligned.m8n8.x4.shared.b16 {%0,%1,%2,%3}, [%4];"
                 : "=r"(r[0]), "=r"(r[1]), "=r"(r[2]), "=r"(r[3]) : "r"(addr));
}
__device__ __forceinline__ void mma_bf16(float* c, const uint32_t* a,
                                         const uint32_t* b) {
    asm volatile("mma.sync.aligned.m16n8k16.row.col.f32.bf16.bf16.f32 "
                 "{%0,%1,%2,%3}, {%4,%5,%6,%7}, {%8,%9}, {%0,%1,%2,%3};"
                 : "+f"(c[0]), "+f"(c[1]), "+f"(c[2]), "+f"(c[3])
                 : "r"(a[0]), "r"(a[1]), "r"(a[2]), "r"(a[3]),
                   "r"(b[0]), "r"(b[1]));
}

// fast exp on FMA/ALU pipes (MUFU is the attention bottleneck at rt=8)
__device__ __forceinline__ float fexp(float x) {
    x = fmaxf(x, -80.0f);
    float y = x * 1.44269504089f;
    float t = y + 12582912.0f;             // rint via magic number
    int   n = __float_as_int(t) - 0x4B400000;
    float fn = t - 12582912.0f;
    float f = y - fn;                      // f in [-0.5, 0.5]
    float r = fmaf(f, 1.3333558e-3f, 9.6181291e-3f);
    r = fmaf(f, r, 5.5504108e-2f);
    r = fmaf(f, r, 2.4022650e-1f);
    r = fmaf(f, r, 6.9314718e-1f);
    r = fmaf(f, r, 1.0f);
    float s = __int_as_float((n + 127) << 23);
    return r * s;
}

// ---------------------------------------------------------------------------
// split: fp32 -> bf16 hi + bf16 lo (residual)
// ---------------------------------------------------------------------------
__global__ __launch_bounds__(256)
void split_kernel(const float* __restrict__ src,
                  __nv_bfloat16* __restrict__ hi,
                  __nv_bfloat16* __restrict__ lo, int n4)
{
    int i = blockIdx.x * 256 + threadIdx.x;
    if (i >= n4) return;
    float4 v = ((const float4*)src)[i];
    uint32_t h01 = bf2(v.x, v.y);
    uint32_t h23 = bf2(v.z, v.w);
    float r0 = v.x - __uint_as_float(h01 << 16);
    float r1 = v.y - __uint_as_float(h01 & 0xffff0000u);
    float r2 = v.z - __uint_as_float(h23 << 16);
    float r3 = v.w - __uint_as_float(h23 & 0xffff0000u);
    ((uint2*)hi)[i] = make_uint2(h01, h23);
    ((uint2*)lo)[i] = make_uint2(bf2(r0, r1), bf2(r2, r3));
}

// ---------------------------------------------------------------------------
// GEMM: Y[m,e] = sum_d A[m,d]*B[e,d] + bias[e], 3-term bf16 split.
// CTA tile 128x256, warp tile 64x64 (8 warps: 2m x 4n), KC=32,
// 4-stage cp.async pipeline, xor-swizzled 64B rows for ldmatrix.
// ---------------------------------------------------------------------------
#define GKC   32
#define GNK   (PD/GKC)          // 32 chunks
#define STGB  49152             // per-stage: Ah 8K | Al 8K | Bh 16K | Bl 16K
#define NSTG  4
#define GEMM_SMEM (NSTG*STGB)   // 192 KB

// swizzled byte offset within a subtile (rows of 32 bf16 = 64B)
__device__ __forceinline__ uint32_t sw_off(int r, int c16) {
    return (uint32_t)(r * 64 + ((c16 ^ ((r >> 1) & 3)) << 4));
}

__device__ __forceinline__ void gemm_load_stage(
    uint32_t sbase, int stage, int kk, int tid,
    const __nv_bfloat16* Ah0, const __nv_bfloat16* Al0,
    const __nv_bfloat16* Bh0, const __nv_bfloat16* Bl0)
{
    const uint32_t sb = sbase + (uint32_t)stage * STGB;
    const int koff = kk * GKC;
    // A: 128 rows x 4 c16-chunks = 512 per matrix -> 2 per thread
#pragma unroll
    for (int it = 0; it < 2; ++it) {
        int ch = tid + 256 * it;
        int r = ch >> 2, c = ch & 3;
        const size_t g = (size_t)r * PD + koff + c * 8;
        uint32_t so = sw_off(r, c);
        cpa16(sb + so,        Ah0 + g);
        cpa16(sb + 8192 + so, Al0 + g);
    }
    // B: 256 rows x 4 = 1024 per matrix -> 4 per thread
#pragma unroll
    for (int it = 0; it < 4; ++it) {
        int ch = tid + 256 * it;
        int r = ch >> 2, c = ch & 3;
        const size_t g = (size_t)r * PD + koff + c * 8;
        uint32_t so = sw_off(r, c);
        cpa16(sb + 16384 + so, Bh0 + g);
        cpa16(sb + 32768 + so, Bl0 + g);
    }
    asm volatile("cp.async.commit_group;" ::: "memory");
}

__global__ __launch_bounds__(256, 1)
void gemm_bf16x3(const __nv_bfloat16* __restrict__ Ah,
                 const __nv_bfloat16* __restrict__ Al,
                 const __nv_bfloat16* __restrict__ Bh,
                 const __nv_bfloat16* __restrict__ Bl,
                 const float* __restrict__ bias,
                 float* __restrict__ Y)
{
    extern __shared__ char smc[];
    const uint32_t sbase = smem_u32(smc);
    const int tid = threadIdx.x;
    const int wid = tid >> 5, lane = tid & 31;
    const int m0 = blockIdx.y * 128, n0 = blockIdx.x * 256;
    const int wm = wid & 1, wn = wid >> 1;   // 2m x 4n warps, each 64x64

    const __nv_bfloat16* Ah0 = Ah + (size_t)m0 * PD;
    const __nv_bfloat16* Al0 = Al + (size_t)m0 * PD;
    const __nv_bfloat16* Bh0 = Bh + (size_t)n0 * PD;
    const __nv_bfloat16* Bl0 = Bl + (size_t)n0 * PD;

    float acc[4][8][4];     // [mi][ni(n8)][frag]
#pragma unroll
    for (int mi = 0; mi < 4; ++mi)
#pragma unroll
        for (int ni = 0; ni < 8; ++ni)
#pragma unroll
            for (int q = 0; q < 4; ++q) acc[mi][ni][q] = 0.f;

    // prologue: stages 0..2
    gemm_load_stage(sbase, 0, 0, tid, Ah0, Al0, Bh0, Bl0);
    gemm_load_stage(sbase, 1, 1, tid, Ah0, Al0, Bh0, Bl0);
    gemm_load_stage(sbase, 2, 2, tid, Ah0, Al0, Bh0, Bl0);

    // ldmatrix lane addressing
    const int a_row  = wm * 64 + (lane & 15);               // + mi*16
    const int a_c16h = lane >> 4;                           // + ks*2
    const int b_row  = wn * 64 + ((lane >> 4) << 3) + (lane & 7);  // + bi*16
    const int b_c16h = (lane >> 3) & 1;                     // + ks*2

    for (int kk = 0; kk < GNK; ++kk) {
        if (kk < GNK - 2)      asm volatile("cp.async.wait_group 2;" ::: "memory");
        else if (kk == GNK - 2) asm volatile("cp.async.wait_group 1;" ::: "memory");
        else                    asm volatile("cp.async.wait_group 0;" ::: "memory");
        __syncthreads();

        if (kk + 3 < GNK)
            gemm_load_stage(sbase, (kk + 3) & 3, kk + 3, tid, Ah0, Al0, Bh0, Bl0);

        const uint32_t sb = sbase + (uint32_t)(kk & 3) * STGB;
#pragma unroll
        for (int ks = 0; ks < 2; ++ks) {
            uint32_t ahi[4][4], alo[4][4];
            const int ac = ks * 2 + a_c16h;
#pragma unroll
            for (int mi = 0; mi < 4; ++mi) {
                uint32_t so = sw_off(a_row + mi * 16, ac);
                ldsm4(ahi[mi], sb + so);
                ldsm4(alo[mi], sb + 8192 + so);
            }
            const int bc = ks * 2 + b_c16h;
#pragma unroll
            for (int bi = 0; bi < 4; ++bi) {
                uint32_t bhi[4], blo[4];
                uint32_t so = sw_off(b_row + bi * 16, bc);
                ldsm4(bhi, sb + 16384 + so);
                ldsm4(blo, sb + 32768 + so);
#pragma unroll
                for (int mi = 0; mi < 4; ++mi) {
#pragma unroll
                    for (int half = 0; half < 2; ++half) {
                        float* c4 = acc[mi][bi * 2 + half];
                        mma_bf16(c4, ahi[mi], &bhi[half * 2]);
                        mma_bf16(c4, ahi[mi], &blo[half * 2]);
                        mma_bf16(c4, alo[mi], &bhi[half * 2]);
                    }
                }
            }
        }
    }

    // epilogue: thread t -> rows (t/4, t/4+8), cols (t%4)*2, +1
    const int trow = lane >> 2;
    const int tcol = (lane & 3) * 2;
#pragma unroll
    for (int mi = 0; mi < 4; ++mi) {
        const int r0 = m0 + wm * 64 + mi * 16 + trow;
#pragma unroll
        for (int ni = 0; ni < 8; ++ni) {
            const int col = n0 + wn * 64 + ni * 8 + tcol;
            float bx = bias[col], by = bias[col + 1];
            float* c4 = acc[mi][ni];
            *(float2*)(Y + (size_t)r0 * PD + col) =
                make_float2(c4[0] + bx, c4[1] + by);
            *(float2*)(Y + (size_t)(r0 + 8) * PD + col) =
                make_float2(c4[2] + bx, c4[3] + by);
        }
    }
}

// ---------------------------------------------------------------------------
// Attention: one CTA per (h,n); thread = batch row. LDS.128 + poly-exp.
// Writes bf16 hi/lo split of output directly.
// ---------------------------------------------------------------------------
#define ATTN_SMEM_FLOATS (PB*PDK + PB*129)
__global__ __launch_bounds__(128)
void attn_kernel(const float* __restrict__ Q, const float* __restrict__ K,
                 const float* __restrict__ V,
                 __nv_bfloat16* __restrict__ Oh,
                 __nv_bfloat16* __restrict__ Ol)
{
    extern __shared__ float smf[];
    float* Ks = smf;              // [128][64]
    float* S  = smf + PB * PDK;   // [128] rows, stride 129

    const int hn = blockIdx.x;
    const int h  = hn >> 8;
    const int n  = hn & 255;
    const int b  = threadIdx.x;
    const size_t rowoff = (size_t)n * PD + h * PDK;

    // gather K -> Ks, Q -> S (staging); 256B-contiguous segments
#pragma unroll
    for (int j = 0; j < 16; ++j) {
        int i = b + 128 * j;
        int r = i >> 4, c4 = i & 15;
        size_t g = (size_t)r * PD * PN + rowoff;
        ((float4*)Ks)[r * 16 + c4] = *((const float4*)(K + g) + c4);
        ((float4*)S )[r * 16 + c4] = *((const float4*)(Q + g) + c4);
    }
    __syncthreads();

    unsigned long long q[32];
    const unsigned long long* qr = (const unsigned long long*)(S + b * PDK);
#pragma unroll
    for (int i = 0; i < 32; ++i) q[i] = qr[i];
    __syncthreads();   // everyone has q before S becomes scores

    float mx = -1e30f;
    for (int c = 0; c < 128; ++c) {
        const ulonglong2* kr = (const ulonglong2*)(Ks + c * PDK);
        unsigned long long a0 = 0ull, a1 = 0ull;
#pragma unroll
        for (int i = 0; i < 16; ++i) {
            ulonglong2 kv = kr[i];
            a0 = ffma2(q[2*i],   kv.x, a0);
            a1 = ffma2(q[2*i+1], kv.y, a1);
        }
        float2 v0 = upk(a0), v1 = upk(a1);
        float s = (v0.x + v0.y + v1.x + v1.y) * 0.125f;
        S[b * 129 + c] = s;
        mx = fmaxf(mx, s);
    }

    float sum = 0.f;
    for (int c = 0; c < 128; ++c) {
        float e = fexp(S[b * 129 + c] - mx);
        S[b * 129 + c] = e;
        sum += e;
    }
    const float inv = 1.0f / sum;
    __syncthreads();

    // overwrite Ks with V
#pragma unroll
    for (int j = 0; j < 16; ++j) {
        int i = b + 128 * j;
        int r = i >> 4, c4 = i & 15;
        size_t g = (size_t)r * PD * PN + rowoff;
        ((float4*)Ks)[r * 16 + c4] = *((const float4*)(V + g) + c4);
    }
    __syncthreads();

    unsigned long long acc[32];
#pragma unroll
    for (int i = 0; i < 32; ++i) acc[i] = 0ull;
    for (int c = 0; c < 128; ++c) {
        float p = S[b * 129 + c];
        unsigned long long pp = pk2(p, p);
        const ulonglong2* vr = (const ulonglong2*)(Ks + c * PDK);
#pragma unroll
        for (int i = 0; i < 16; ++i) {
            ulonglong2 vv = vr[i];
            acc[2*i]   = ffma2(pp, vv.x, acc[2*i]);
            acc[2*i+1] = ffma2(pp, vv.y, acc[2*i+1]);
        }
    }

    // write hi/lo bf16 split of output at (b*PN+n)*PD + h*64
    const size_t obase = ((size_t)(b * PN + n)) * PD + h * PDK;
#pragma unroll
    for (int i = 0; i < 32; i += 2) {
        float2 x = upk(acc[i]);
        float2 y = upk(acc[i + 1]);
        float f0 = x.x * inv, f1 = x.y * inv;
        float f2 = y.x * inv, f3 = y.y * inv;
        uint32_t h01 = bf2(f0, f1), h23 = bf2(f2, f3);
        float r0 = f0 - __uint_as_float(h01 << 16);
        float r1 = f1 - __uint_as_float(h01 & 0xffff0000u);
        float r2 = f2 - __uint_as_float(h23 << 16);
        float r3 = f3 - __uint_as_float(h23 & 0xffff0000u);
        ((uint2*)(Oh + obase))[i >> 1] = make_uint2(h01, h23);
        ((uint2*)(Ol + obase))[i >> 1] = make_uint2(bf2(r0, r1), bf2(r2, r3));
    }
}

// ---------------------------------------------------------------------------
extern "C" void kernel_launch(void* const* d_in, const int* in_sizes, int n_in,
                              void* d_out, int out_size)
{
    const float* query = (const float*)d_in[0];
    const float* key_i = (const float*)d_in[1];
    const float* value = (const float*)d_in[2];
    const float* Wq = (const float*)d_in[3];
    const float* bq = (const float*)d_in[4];
    const float* Wk = (const float*)d_in[5];
    const float* bk = (const float*)d_in[6];
    const float* Wv = (const float*)d_in[7];
    const float* bv = (const float*)d_in[8];
    const float* Wo = (const float*)d_in[9];
    const float* bo = (const float*)d_in[10];
    float* out = (float*)d_out;

    float *gQ, *gK, *gV;
    cudaGetSymbolAddress((void**)&gQ, g_Q);
    cudaGetSymbolAddress((void**)&gK, g_K);
    cudaGetSymbolAddress((void**)&gV, g_V);
    __nv_bfloat16 *qh, *ql, *kh, *kl, *vh, *vl, *oh, *ol, *wh, *wl;
    cudaGetSymbolAddress((void**)&qh, g_qh);
    cudaGetSymbolAddress((void**)&ql, g_ql);
    cudaGetSymbolAddress((void**)&kh, g_kh);
    cudaGetSymbolAddress((void**)&kl, g_kl);
    cudaGetSymbolAddress((void**)&vh, g_vh);
    cudaGetSymbolAddress((void**)&vl, g_vl);
    cudaGetSymbolAddress((void**)&oh, g_oh);
    cudaGetSymbolAddress((void**)&ol, g_ol);
    cudaGetSymbolAddress((void**)&wh, g_wh);
    cudaGetSymbolAddress((void**)&wl, g_wl);

    cudaFuncSetAttribute(gemm_bf16x3,
                         cudaFuncAttributeMaxDynamicSharedMemorySize, GEMM_SMEM);
    const size_t attn_smem = (size_t)ATTN_SMEM_FLOATS * sizeof(float);
    cudaFuncSetAttribute(attn_kernel,
                         cudaFuncAttributeMaxDynamicSharedMemorySize,
                         (int)attn_smem);

    const int nbig = PM * PD / 4, nw = PD * PD / 4;

    split_kernel<<<nbig / 256, 256>>>(query, qh, ql, nbig);
    split_kernel<<<nbig / 256, 256>>>(key_i, kh, kl, nbig);
    split_kernel<<<nbig / 256, 256>>>(value, vh, vl, nbig);
    split_kernel<<<nw / 256, 256>>>(Wq, wh + 0 * (size_t)PD * PD, wl + 0 * (size_t)PD * PD, nw);
    split_kernel<<<nw / 256, 256>>>(Wk, wh + 1 * (size_t)PD * PD, wl + 1 * (size_t)PD * PD, nw);
    split_kernel<<<nw / 256, 256>>>(Wv, wh + 2 * (size_t)PD * PD, wl + 2 * (size_t)PD * PD, nw);
    split_kernel<<<nw / 256, 256>>>(Wo, wh + 3 * (size_t)PD * PD, wl + 3 * (size_t)PD * PD, nw);

    dim3 gg(PD / 256, PM / 128);   // (4, 256)
    gemm_bf16x3<<<gg, 256, GEMM_SMEM>>>(qh, ql, wh + 0 * (size_t)PD * PD, wl + 0 * (size_t)PD * PD, bq, gQ);
    gemm_bf16x3<<<gg, 256, GEMM_SMEM>>>(kh, kl, wh + 1 * (size_t)PD * PD, wl + 1 * (size_t)PD * PD, bk, gK);
    gemm_bf16x3<<<gg, 256, GEMM_SMEM>>>(vh, vl, wh + 2 * (size_t)PD * PD, wl + 2 * (size_t)PD * PD, bv, gV);

    attn_kernel<<<PH * PN, 128, attn_smem>>>(gQ, gK, gV, oh, ol);

    gemm_bf16x3<<<gg, 256, GEMM_SMEM>>>(oh, ol, wh + 3 * (size_t)PD * PD, wl + 3 * (size_t)PD * PD, bo, out);
}